// round 2
// baseline (speedup 1.0000x reference)
#include <cuda_runtime.h>
#include <math.h>

// Problem constants
#define B_   128
#define CIN  3
#define COUT 16
#define HW   (256 * 256)          // 65536 elements per plane
#define PLANE_F4 (HW / 4)         // 16384 float4 per plane
#define NPLANES (B_ * CIN)        // 384
#define BLOCKS_PER_PLANE 4
#define THREADS 256
#define NBLOCKS (NPLANES * BLOCKS_PER_PLANE)                   // 1536
#define F4_PER_THREAD (PLANE_F4 / BLOCKS_PER_PLANE / THREADS)  // 16

// Scratch (device globals — no allocation allowed).
// Per-(plane,chunk) partial sums, written with plain stores: no zero pass needed.
__device__ float    g_partial[NBLOCKS];
__device__ unsigned g_count;   // zero-initialized; last block resets it -> replay-safe

__global__ __launch_bounds__(THREADS) void k_fused(
    const float4* __restrict__ x,
    const float*  __restrict__ weight,
    const float*  __restrict__ bias,
    float*        __restrict__ out)
{
    // ---- Phase 1: every block sum-reduces its 16K-element chunk ----
    const int plane = blockIdx.x / BLOCKS_PER_PLANE;
    const int chunk = blockIdx.x % BLOCKS_PER_PLANE;
    const float4* base = x + (size_t)plane * PLANE_F4
                           + (size_t)chunk * (PLANE_F4 / BLOCKS_PER_PLANE);

    float s = 0.0f;
    #pragma unroll
    for (int i = 0; i < F4_PER_THREAD; i++) {
        float4 v = base[threadIdx.x + i * THREADS];
        s += (v.x + v.y) + (v.z + v.w);
    }

    // warp reduce
    #pragma unroll
    for (int o = 16; o > 0; o >>= 1)
        s += __shfl_xor_sync(0xFFFFFFFFu, s, o);

    __shared__ float ws[THREADS / 32];
    if ((threadIdx.x & 31) == 0) ws[threadIdx.x >> 5] = s;
    __syncthreads();

    __shared__ bool s_last;
    if (threadIdx.x == 0) {
        float t = 0.0f;
        #pragma unroll
        for (int w = 0; w < THREADS / 32; w++) t += ws[w];
        g_partial[blockIdx.x] = t;
        __threadfence();                          // make partial visible
        unsigned ticket = atomicAdd(&g_count, 1u);
        s_last = (ticket == NBLOCKS - 1);
    }
    __syncthreads();

    if (!s_last) return;

    // ---- Phase 2: only the last-finishing block runs the epilogue ----
    __threadfence();  // acquire: order reads of g_partial after the fence/atomic

    const int t = threadIdx.x;

    // Plane sums: 384 planes, 4 partials each
    __shared__ float S[NPLANES];
    for (int p = t; p < NPLANES; p += THREADS) {
        const float* gp = &g_partial[p * BLOCKS_PER_PLANE];
        S[p] = (gp[0] + gp[1]) + (gp[2] + gp[3]);
    }

    // Kernel-weight sums per (ci, co)
    __shared__ float wsum[CIN][COUT];
    if (t < CIN * COUT) {
        int ci = t / COUT, co = t % COUT;
        float acc = 0.0f;
        #pragma unroll
        for (int pq = 0; pq < 9; pq++)
            acc += weight[(ci * COUT + co) * 9 + pq];
        wsum[ci][co] = acc;
    }
    __syncthreads();

    if (t < B_) {
        const float s0 = S[t * 3 + 0];
        const float s1 = S[t * 3 + 1];
        const float s2 = S[t * 3 + 2];
        const float inv = 1.0f / (258.0f * 258.0f);

        float y[COUT];
        float m = -INFINITY;
        #pragma unroll
        for (int co = 0; co < COUT; co++) {
            float v = (s0 * wsum[0][co] + s1 * wsum[1][co] + s2 * wsum[2][co]) * inv
                      + bias[co];
            y[co] = v;
            m = fmaxf(m, v);
        }
        float e = 0.0f;
        #pragma unroll
        for (int co = 0; co < COUT; co++)
            e += expf(y[co] - m);

        out[t] = 10.0f * (m + logf(e));
    }

    if (t == 0) g_count = 0;   // reset for next (graph-replayed) launch
}

extern "C" void kernel_launch(void* const* d_in, const int* in_sizes, int n_in,
                              void* d_out, int out_size) {
    const float4* x      = (const float4*)d_in[0];
    const float*  weight = (const float*)d_in[1];
    const float*  bias   = (const float*)d_in[2];
    float* out = (float*)d_out;

    k_fused<<<NBLOCKS, THREADS>>>(x, weight, bias, out);
}

// round 3
// speedup vs baseline: 1.1142x; 1.1142x over previous
#include <cuda_runtime.h>
#include <math.h>

// Problem constants
#define B_   128
#define CIN  3
#define COUT 16
#define HW   (256 * 256)          // 65536 elements per plane
#define PLANE_F4 (HW / 4)         // 16384 float4 per plane
#define NPLANES (B_ * CIN)        // 384
#define BLOCKS_PER_PLANE 4
#define THREADS 256
#define NBLOCKS (NPLANES * BLOCKS_PER_PLANE)                   // 1536
#define F4_PER_THREAD (PLANE_F4 / BLOCKS_PER_PLANE / THREADS)  // 16

// Per-(plane,chunk) partial sums — plain stores, no zeroing, no atomics.
__device__ float g_partial[NBLOCKS];

__global__ __launch_bounds__(THREADS) void k_reduce(const float4* __restrict__ x) {
    const int plane = blockIdx.x / BLOCKS_PER_PLANE;
    const int chunk = blockIdx.x % BLOCKS_PER_PLANE;
    const float4* base = x + (size_t)plane * PLANE_F4
                           + (size_t)chunk * (PLANE_F4 / BLOCKS_PER_PLANE);

    float s = 0.0f;
    #pragma unroll
    for (int i = 0; i < F4_PER_THREAD; i++) {
        float4 v = base[threadIdx.x + i * THREADS];
        s += (v.x + v.y) + (v.z + v.w);
    }

    // warp reduce
    #pragma unroll
    for (int o = 16; o > 0; o >>= 1)
        s += __shfl_xor_sync(0xFFFFFFFFu, s, o);

    __shared__ float ws[THREADS / 32];
    if ((threadIdx.x & 31) == 0) ws[threadIdx.x >> 5] = s;
    __syncthreads();

    if (threadIdx.x == 0) {
        float t = 0.0f;
        #pragma unroll
        for (int w = 0; w < THREADS / 32; w++) t += ws[w];
        g_partial[blockIdx.x] = t;      // plain store; next kernel orders via launch dep
    }
}

// Epilogue: combine partials -> plane sums -> mean+bias -> logsumexp -> *10.
// One block; partials are L2-resident (6 KB just written).
__global__ __launch_bounds__(256) void k_final(
    const float* __restrict__ weight,
    const float* __restrict__ bias,
    float*       __restrict__ out)
{
    const int t = threadIdx.x;

    // Plane sums: 384 planes x 4 partials. 256 threads -> 1.5 planes each.
    __shared__ float S[NPLANES];
    for (int p = t; p < NPLANES; p += 256) {
        const float4 v = *reinterpret_cast<const float4*>(&g_partial[p * BLOCKS_PER_PLANE]);
        S[p] = (v.x + v.y) + (v.z + v.w);
    }

    // Kernel-weight sums per (ci, co)
    __shared__ float wsum[CIN][COUT];
    if (t < CIN * COUT) {
        int ci = t / COUT, co = t % COUT;
        float acc = 0.0f;
        #pragma unroll
        for (int pq = 0; pq < 9; pq++)
            acc += weight[(ci * COUT + co) * 9 + pq];
        wsum[ci][co] = acc;
    }
    __syncthreads();

    if (t < B_) {
        const float s0 = S[t * 3 + 0];
        const float s1 = S[t * 3 + 1];
        const float s2 = S[t * 3 + 2];
        const float inv = 1.0f / (258.0f * 258.0f);

        float y[COUT];
        float m = -INFINITY;
        #pragma unroll
        for (int co = 0; co < COUT; co++) {
            float v = (s0 * wsum[0][co] + s1 * wsum[1][co] + s2 * wsum[2][co]) * inv
                      + bias[co];
            y[co] = v;
            m = fmaxf(m, v);
        }
        float e = 0.0f;
        #pragma unroll
        for (int co = 0; co < COUT; co++)
            e += expf(y[co] - m);

        out[t] = 10.0f * (m + logf(e));
    }
}

extern "C" void kernel_launch(void* const* d_in, const int* in_sizes, int n_in,
                              void* d_out, int out_size) {
    const float4* x      = (const float4*)d_in[0];
    const float*  weight = (const float*)d_in[1];
    const float*  bias   = (const float*)d_in[2];
    float* out = (float*)d_out;

    k_reduce<<<NBLOCKS, THREADS>>>(x);
    k_final<<<1, 256>>>(weight, bias, out);
}

// round 4
// speedup vs baseline: 1.1489x; 1.0311x over previous
#include <cuda_runtime.h>
#include <math.h>

// Problem constants
#define B_   128
#define CIN  3
#define COUT 16
#define HW   (256 * 256)          // 65536 elements per plane
#define PLANE_F4 (HW / 4)         // 16384 float4 per plane
#define NPLANES (B_ * CIN)        // 384
#define BLOCKS_PER_PLANE 4
#define THREADS 256
#define NBLOCKS (NPLANES * BLOCKS_PER_PLANE)                   // 1536
#define F4_PER_THREAD (PLANE_F4 / BLOCKS_PER_PLANE / THREADS)  // 16

// Per-(plane,chunk) partial sums — plain stores, no zeroing, no atomics.
__device__ float g_partial[NBLOCKS];

__global__ __launch_bounds__(THREADS) void k_reduce(const float4* __restrict__ x) {
    const int plane = blockIdx.x / BLOCKS_PER_PLANE;
    const int chunk = blockIdx.x % BLOCKS_PER_PLANE;
    const float4* base = x + (size_t)plane * PLANE_F4
                           + (size_t)chunk * (PLANE_F4 / BLOCKS_PER_PLANE);

    float s = 0.0f;
    #pragma unroll
    for (int i = 0; i < F4_PER_THREAD; i++) {
        float4 v = base[threadIdx.x + i * THREADS];
        s += (v.x + v.y) + (v.z + v.w);
    }

    // warp reduce
    #pragma unroll
    for (int o = 16; o > 0; o >>= 1)
        s += __shfl_xor_sync(0xFFFFFFFFu, s, o);

    __shared__ float ws[THREADS / 32];
    if ((threadIdx.x & 31) == 0) ws[threadIdx.x >> 5] = s;
    __syncthreads();

    if (threadIdx.x == 0) {
        float t = 0.0f;
        #pragma unroll
        for (int w = 0; w < THREADS / 32; w++) t += ws[w];
        g_partial[blockIdx.x] = t;
    }
    __syncthreads();
    // PDL: signal dependent grid may complete its wait; writes above are
    // made visible to the dependent grid per the PDL memory model.
    cudaTriggerProgrammaticLaunchCompletion();
}

// Epilogue (PDL secondary): launched concurrently with k_reduce's tail.
// Everything not depending on g_partial runs BEFORE the grid-dep wait.
__global__ __launch_bounds__(128) void k_final(
    const float* __restrict__ weight,
    const float* __restrict__ bias,
    float*       __restrict__ out)
{
    const int t = threadIdx.x;

    // --- independent work: kernel-weight sums + bias load (overlaps primary) ---
    __shared__ float wsum[CIN][COUT];
    if (t < CIN * COUT) {
        int ci = t / COUT, co = t % COUT;
        float acc = 0.0f;
        #pragma unroll
        for (int pq = 0; pq < 9; pq++)
            acc += weight[(ci * COUT + co) * 9 + pq];
        wsum[ci][co] = acc;
    }
    const float b_local[1] = {0};  (void)b_local;
    __syncthreads();

    float w0[COUT], w1[COUT], w2[COUT];
    #pragma unroll
    for (int co = 0; co < COUT; co++) {
        w0[co] = wsum[0][co];
        w1[co] = wsum[1][co];
        w2[co] = wsum[2][co];
    }
    // bias into registers too (independent of primary)
    float bch[COUT];
    #pragma unroll
    for (int co = 0; co < COUT; co++) bch[co] = bias[co];

    // --- wait for k_reduce's partials to be visible ---
    cudaGridDependencySynchronize();

    // thread t = batch index: read its 3 planes x 4 chunks directly (L2-hot)
    const float4 p0 = *reinterpret_cast<const float4*>(&g_partial[(t * 3 + 0) * 4]);
    const float4 p1 = *reinterpret_cast<const float4*>(&g_partial[(t * 3 + 1) * 4]);
    const float4 p2 = *reinterpret_cast<const float4*>(&g_partial[(t * 3 + 2) * 4]);
    const float s0 = (p0.x + p0.y) + (p0.z + p0.w);
    const float s1 = (p1.x + p1.y) + (p1.z + p1.w);
    const float s2 = (p2.x + p2.y) + (p2.z + p2.w);
    const float inv = 1.0f / (258.0f * 258.0f);

    float y[COUT];
    float m = -INFINITY;
    #pragma unroll
    for (int co = 0; co < COUT; co++) {
        float v = (s0 * w0[co] + s1 * w1[co] + s2 * w2[co]) * inv + bch[co];
        y[co] = v;
        m = fmaxf(m, v);
    }
    float e = 0.0f;
    #pragma unroll
    for (int co = 0; co < COUT; co++)
        e += expf(y[co] - m);

    out[t] = 10.0f * (m + logf(e));
}

extern "C" void kernel_launch(void* const* d_in, const int* in_sizes, int n_in,
                              void* d_out, int out_size) {
    const float4* x      = (const float4*)d_in[0];
    const float*  weight = (const float*)d_in[1];
    const float*  bias   = (const float*)d_in[2];
    float* out = (float*)d_out;

    k_reduce<<<NBLOCKS, THREADS>>>(x);

    // Launch k_final as a PDL secondary: its prologue overlaps k_reduce's tail.
    cudaLaunchConfig_t cfg = {};
    cfg.gridDim  = dim3(1, 1, 1);
    cfg.blockDim = dim3(128, 1, 1);
    cfg.dynamicSmemBytes = 0;
    cfg.stream = 0;  // same (legacy default) stream as k_reduce
    cudaLaunchAttribute attrs[1];
    attrs[0].id = cudaLaunchAttributeProgrammaticStreamSerialization;
    attrs[0].val.programmaticStreamSerializationAllowed = 1;
    cfg.attrs = attrs;
    cfg.numAttrs = 1;
    cudaLaunchKernelEx(&cfg, k_final, weight, bias, out);
}

// round 6
// speedup vs baseline: 1.2957x; 1.1278x over previous
#include <cuda_runtime.h>
#include <math.h>

// Problem constants
#define B_   128
#define CIN  3
#define COUT 16
#define HW   (256 * 256)          // 65536 elements per plane
#define PLANE_F4 (HW / 4)         // 16384 float4 per plane
#define NPLANES (B_ * CIN)        // 384
#define BLOCKS_PER_PLANE 2
#define THREADS 256
#define NBLOCKS (NPLANES * BLOCKS_PER_PLANE)                   // 768 -> single wave
#define F4_PER_THREAD (PLANE_F4 / BLOCKS_PER_PLANE / THREADS)  // 32

// Per-(plane,chunk) partial sums — plain stores, no zeroing, no atomics.
__device__ float g_partial[NBLOCKS];

__global__ __launch_bounds__(THREADS) void k_reduce(const float4* __restrict__ x) {
    const int plane = blockIdx.x >> 1;
    const int chunk = blockIdx.x & 1;
    const float4* base = x + (size_t)plane * PLANE_F4
                           + (size_t)chunk * (PLANE_F4 / BLOCKS_PER_PLANE);

    float s = 0.0f;
    #pragma unroll 16
    for (int i = 0; i < F4_PER_THREAD; i++) {
        float4 v = base[threadIdx.x + i * THREADS];
        s += (v.x + v.y) + (v.z + v.w);
    }

    // warp reduce
    #pragma unroll
    for (int o = 16; o > 0; o >>= 1)
        s += __shfl_xor_sync(0xFFFFFFFFu, s, o);

    __shared__ float ws[THREADS / 32];
    if ((threadIdx.x & 31) == 0) ws[threadIdx.x >> 5] = s;
    __syncthreads();

    if (threadIdx.x == 0) {
        float t = 0.0f;
        #pragma unroll
        for (int w = 0; w < THREADS / 32; w++) t += ws[w];
        g_partial[blockIdx.x] = t;
    }
    __syncthreads();
    // PDL: make writes visible to the dependent grid and let it proceed.
    cudaTriggerProgrammaticLaunchCompletion();
}

// Epilogue (PDL secondary): prologue overlaps k_reduce's tail.
__global__ __launch_bounds__(128) void k_final(
    const float* __restrict__ weight,
    const float* __restrict__ bias,
    float*       __restrict__ out)
{
    const int t = threadIdx.x;

    // --- independent work (overlaps primary): kernel-weight sums + bias ---
    __shared__ float wsum[CIN][COUT];
    if (t < CIN * COUT) {
        int ci = t / COUT, co = t % COUT;
        float acc = 0.0f;
        #pragma unroll
        for (int pq = 0; pq < 9; pq++)
            acc += weight[(ci * COUT + co) * 9 + pq];
        wsum[ci][co] = acc;
    }
    __syncthreads();

    float w0[COUT], w1[COUT], w2[COUT], bch[COUT];
    #pragma unroll
    for (int co = 0; co < COUT; co++) {
        w0[co] = wsum[0][co];
        w1[co] = wsum[1][co];
        w2[co] = wsum[2][co];
        bch[co] = bias[co];
    }

    // --- wait for k_reduce's partials ---
    cudaGridDependencySynchronize();

    // thread t = batch index: 3 planes x 2 chunks = 6 partials starting at
    // g_partial[t*6]. All three pair-starts are even indices -> 8B-aligned
    // float2 loads (a float4 here would be misaligned for odd t).
    const float2 pa = *reinterpret_cast<const float2*>(&g_partial[t * 6 + 0]);
    const float2 pb = *reinterpret_cast<const float2*>(&g_partial[t * 6 + 2]);
    const float2 pc = *reinterpret_cast<const float2*>(&g_partial[t * 6 + 4]);
    const float s0 = pa.x + pa.y;
    const float s1 = pb.x + pb.y;
    const float s2 = pc.x + pc.y;
    const float inv = 1.0f / (258.0f * 258.0f);

    float y[COUT];
    float m = -INFINITY;
    #pragma unroll
    for (int co = 0; co < COUT; co++) {
        float v = (s0 * w0[co] + s1 * w1[co] + s2 * w2[co]) * inv + bch[co];
        y[co] = v;
        m = fmaxf(m, v);
    }
    float e = 0.0f;
    #pragma unroll
    for (int co = 0; co < COUT; co++)
        e += expf(y[co] - m);

    out[t] = 10.0f * (m + logf(e));
}

extern "C" void kernel_launch(void* const* d_in, const int* in_sizes, int n_in,
                              void* d_out, int out_size) {
    const float4* x      = (const float4*)d_in[0];
    const float*  weight = (const float*)d_in[1];
    const float*  bias   = (const float*)d_in[2];
    float* out = (float*)d_out;

    k_reduce<<<NBLOCKS, THREADS>>>(x);

    cudaLaunchConfig_t cfg = {};
    cfg.gridDim  = dim3(1, 1, 1);
    cfg.blockDim = dim3(128, 1, 1);
    cfg.dynamicSmemBytes = 0;
    cfg.stream = 0;
    cudaLaunchAttribute attrs[1];
    attrs[0].id = cudaLaunchAttributeProgrammaticStreamSerialization;
    attrs[0].val.programmaticStreamSerializationAllowed = 1;
    cfg.attrs = attrs;
    cfg.numAttrs = 1;
    cudaLaunchKernelEx(&cfg, k_final, weight, bias, out);
}